// round 15
// baseline (speedup 1.0000x reference)
#include <cuda_runtime.h>
#include <cuda_fp16.h>
#include <cstdint>

#define N_NODES 20000
#define D_IN 512
#define D_OUT 64
#define N_EDGES 160000

// ---------------------------------------------------------------------------
// device globals (no allocation allowed)
// ---------------------------------------------------------------------------
__device__ float g_buf0[(size_t)N_NODES * D_IN];   // h1 fp32, later z fp32
__device__ float g_buf1[(size_t)N_NODES * D_IN];   // h2 fp32
__device__ __half g_x_h[(size_t)N_NODES * D_IN];   // x rounded to fp16
__device__ int g_deg[N_NODES];
__device__ int g_off[N_NODES + 1];
__device__ int g_cursor[N_NODES];
__device__ int g_adj[N_EDGES];
__device__ __half g_w1_h[D_IN * D_IN];
__device__ __half g_w2_h[D_OUT * D_IN];

// ---------------------------------------------------------------------------
// CSR build
// ---------------------------------------------------------------------------
__global__ void csr_zero_deg(int* deg) {
    int i = blockIdx.x * blockDim.x + threadIdx.x;
    if (i < N_NODES) deg[i] = 0;
}
__global__ void csr_hist(const int* __restrict__ dst, int* __restrict__ deg) {
    int e = blockIdx.x * blockDim.x + threadIdx.x;
    if (e < N_EDGES) atomicAdd(&deg[dst[e]], 1);
}

// Single-block exclusive scan, warp-shuffle based (2 barriers total).
__global__ void csr_scan(const int* __restrict__ deg, int* __restrict__ off,
                         int* __restrict__ cursor) {
    __shared__ int wsum[32];
    const int t = threadIdx.x;
    const int lane = t & 31;
    const int warp = t >> 5;
    const int ITEMS = 20;            // 1024*20 >= 20000
    int base = t * ITEMS;
    int local[ITEMS];
    int s = 0;
#pragma unroll
    for (int i = 0; i < ITEMS; i++) {
        int idx = base + i;
        int v = (idx < N_NODES) ? deg[idx] : 0;
        local[i] = s;
        s += v;
    }
    // inclusive warp scan of per-thread sums
    int incl = s;
#pragma unroll
    for (int d = 1; d < 32; d <<= 1) {
        int v = __shfl_up_sync(0xffffffffu, incl, d);
        if (lane >= d) incl += v;
    }
    if (lane == 31) wsum[warp] = incl;
    __syncthreads();
    if (warp == 0) {
        int v = wsum[lane];
        int winc = v;
#pragma unroll
        for (int d = 1; d < 32; d <<= 1) {
            int u = __shfl_up_sync(0xffffffffu, winc, d);
            if (lane >= d) winc += u;
        }
        wsum[lane] = winc - v;  // exclusive warp base
    }
    __syncthreads();
    const int tbase = wsum[warp] + (incl - s);
#pragma unroll
    for (int i = 0; i < ITEMS; i++) {
        int idx = base + i;
        if (idx < N_NODES) {
            int o = tbase + local[i];
            off[idx] = o;
            cursor[idx] = o;
        }
    }
    if (t == 1023) off[N_NODES] = tbase + s;
}

__global__ void csr_fill(const int* __restrict__ src, const int* __restrict__ dst,
                         int* __restrict__ cursor, int* __restrict__ adj) {
    int e = blockIdx.x * blockDim.x + threadIdx.x;
    if (e < N_EDGES) {
        int p = atomicAdd(&cursor[dst[e]], 1);
        adj[p] = src[e];
    }
}

// ---------------------------------------------------------------------------
// Merged rounding: x, W1, W2 -> fp16 in one kernel
// ---------------------------------------------------------------------------
#define N4_X (N_NODES * D_IN / 4)     // 2,560,000
#define N4_W1 (D_IN * D_IN / 4)       // 65,536
#define N4_W2 (D_OUT * D_IN / 4)      // 8,192
#define N4_ALL (N4_X + N4_W1 + N4_W2)

__device__ __forceinline__ uint2 f4_to_h4(float4 v) {
    union { __half2 h2[2]; uint2 u; } o;
    o.h2[0] = __floats2half2_rn(v.x, v.y);
    o.h2[1] = __floats2half2_rn(v.z, v.w);
    return o.u;
}

__global__ void round_all(const float4* __restrict__ x,
                          const float4* __restrict__ w1,
                          const float4* __restrict__ w2,
                          uint2* __restrict__ xh,
                          uint2* __restrict__ w1h,
                          uint2* __restrict__ w2h) {
    int i = blockIdx.x * blockDim.x + threadIdx.x;
    if (i < N4_X) {
        xh[i] = f4_to_h4(x[i]);
    } else if (i < N4_X + N4_W1) {
        int j = i - N4_X;
        w1h[j] = f4_to_h4(w1[j]);
    } else if (i < N4_ALL) {
        int j = i - N4_X - N4_W1;
        w2h[j] = f4_to_h4(w2[j]);
    }
}

// ---------------------------------------------------------------------------
// Gather propagate: fp16 x in via uint4 (8 halves/load), fp32 out.
// 64 threads per node, 2 nodes per 128-thread block. Halves LSU issue count.
// ---------------------------------------------------------------------------
__global__ void gather_prop_h(const uint4* __restrict__ xh,  // [N, 64] uint4
                              const int* __restrict__ off,
                              const int* __restrict__ adj,
                              float4* __restrict__ out) {    // [N, 128] float4
    const int node = blockIdx.x * 2 + (threadIdx.x >> 6);
    const int t = threadIdx.x & 63;
    if (node >= N_NODES) return;
    int b = off[node];
    int e = off[node + 1];
    float acc[8] = {0.f, 0.f, 0.f, 0.f, 0.f, 0.f, 0.f, 0.f};

    auto add8 = [&](uint4 v) {
        union { uint4 u; __half2 h[4]; } w;
        w.u = v;
#pragma unroll
        for (int j = 0; j < 4; j++) {
            float2 f = __half22float2(w.h[j]);
            acc[2 * j] += f.x;
            acc[2 * j + 1] += f.y;
        }
    };

    int i = b;
    for (; i + 1 < e; i += 2) {
        uint4 v0 = xh[(size_t)adj[i] * 64 + t];
        uint4 v1 = xh[(size_t)adj[i + 1] * 64 + t];
        add8(v0);
        add8(v1);
    }
    if (i < e) add8(xh[(size_t)adj[i] * 64 + t]);

    float4* op = out + (size_t)node * 128 + t * 2;
    op[0] = make_float4(acc[0], acc[1], acc[2], acc[3]);
    op[1] = make_float4(acc[4], acc[5], acc[6], acc[7]);
}

// ---------------------------------------------------------------------------
// Gather propagate 64-wide + fused log_softmax (one warp per node).
// Lane owns cols {2*lane, 2*lane+1} -> float2 loads/stores (32 loads/row).
// ---------------------------------------------------------------------------
__global__ void gather64_softmax(const float* __restrict__ z,
                                 const int* __restrict__ off,
                                 const int* __restrict__ adj,
                                 float* __restrict__ out) {
    const int node = blockIdx.x * (blockDim.x >> 5) + (threadIdx.x >> 5);
    const int lane = threadIdx.x & 31;
    if (node >= N_NODES) return;
    int b = off[node];
    int e = off[node + 1];
    float a0 = 0.f, a1 = 0.f;
    for (int i = b; i < e; i++) {
        float2 v = *reinterpret_cast<const float2*>(
            z + (size_t)adj[i] * D_OUT + lane * 2);
        a0 += v.x;
        a1 += v.y;
    }
    float mx = fmaxf(a0, a1);
#pragma unroll
    for (int o = 16; o > 0; o >>= 1)
        mx = fmaxf(mx, __shfl_xor_sync(0xffffffffu, mx, o));
    float s = expf(a0 - mx) + expf(a1 - mx);
#pragma unroll
    for (int o = 16; o > 0; o >>= 1)
        s += __shfl_xor_sync(0xffffffffu, s, o);
    float l = mx + logf(s);
    *reinterpret_cast<float2*>(out + (size_t)node * D_OUT + lane * 2) =
        make_float2(a0 - l, a1 - l);
}

// ---------------------------------------------------------------------------
// mma.sync helpers (fp16 inputs, fp32 accumulate)
// ---------------------------------------------------------------------------
__device__ __forceinline__ void mma_fp16(float* d, const uint32_t* a,
                                         const uint32_t* b) {
    asm volatile(
        "mma.sync.aligned.m16n8k16.row.col.f32.f16.f16.f32 "
        "{%0,%1,%2,%3}, {%4,%5,%6,%7}, {%8,%9}, {%0,%1,%2,%3};"
        : "+f"(d[0]), "+f"(d[1]), "+f"(d[2]), "+f"(d[3])
        : "r"(a[0]), "r"(a[1]), "r"(a[2]), "r"(a[3]), "r"(b[0]), "r"(b[1]));
}

__device__ __forceinline__ void ldmx4(uint32_t* r, uint32_t addr) {
    asm volatile(
        "ldmatrix.sync.aligned.m8n8.x4.shared.b16 {%0,%1,%2,%3}, [%4];"
        : "=r"(r[0]), "=r"(r[1]), "=r"(r[2]), "=r"(r[3])
        : "r"(addr));
}

// ---------------------------------------------------------------------------
// fp16 2-term split GEMM via mma.sync: C[M,N] = A[M,512] * B[N,512]^T
// A fp32 -> fp16 hi+lo inline; B pre-rounded fp16.
// CTA tile 128 x BN, BK=32, 8 warps each 32 x (BN/2).
// ---------------------------------------------------------------------------
#define LDS_STRIDE 80

template <int BN, bool RELU>
__global__ __launch_bounds__(256)
void gemm_mma(const float* __restrict__ A,
              const __half* __restrict__ Bh,
              float* __restrict__ C, int M, int N) {
    constexpr int NI = BN / 16;
    constexpr int NG = BN / 32;
    constexpr int SM_AH = 0;
    constexpr int SM_AL = 128 * LDS_STRIDE;
    constexpr int SM_BH = 2 * 128 * LDS_STRIDE;
    constexpr int SM_TOTAL = SM_BH + BN * LDS_STRIDE;
    constexpr int BPR = 256 / BN;
    constexpr int BVEC = 4 / BPR;

    __shared__ __align__(16) char smem[SM_TOTAL];
    const int tid = threadIdx.x;
    const int lane = tid & 31;
    const int wid = tid >> 5;
    const int wm = wid & 3;
    const int wn = wid >> 2;
    const int m0 = blockIdx.x * 128;
    const int n0 = blockIdx.y * BN;

    const uint32_t sb = (uint32_t)__cvta_generic_to_shared(smem);

    float acc[2][NI][4];
#pragma unroll
    for (int i = 0; i < 2; i++)
#pragma unroll
        for (int j = 0; j < NI; j++)
#pragma unroll
            for (int k = 0; k < 4; k++) acc[i][j][k] = 0.f;

    const int ar = tid >> 1;
    const int ah = tid & 1;
    const bool arow_ok = (m0 + ar) < M;
    const int br = tid / BPR;
    const int bq = tid % BPR;

    const uint32_t a_lm = sb + (uint32_t)((wm * 32 + (lane & 15)) * LDS_STRIDE +
                                          (lane >> 4) * 16);
    const uint32_t b_lm = sb + SM_BH +
        (uint32_t)((wn * (BN / 2) + (lane & 15)) * LDS_STRIDE + (lane >> 4) * 16);

    float4 av[4];
    uint4 bhv[BVEC];

    auto load_tile = [&](int kc) {
        if (arow_ok) {
            const float4* ap = reinterpret_cast<const float4*>(
                A + (size_t)(m0 + ar) * D_IN + kc * 32 + ah * 16);
#pragma unroll
            for (int i = 0; i < 4; i++) av[i] = ap[i];
        } else {
#pragma unroll
            for (int i = 0; i < 4; i++) av[i] = make_float4(0.f, 0.f, 0.f, 0.f);
        }
        const uint4* bh = reinterpret_cast<const uint4*>(
            Bh + (size_t)(n0 + br) * D_IN + kc * 32 + bq * (8 * BVEC));
#pragma unroll
        for (int i = 0; i < BVEC; i++) bhv[i] = bh[i];
    };

    load_tile(0);

    for (int kc = 0; kc < 16; kc++) {
        __syncthreads();

        {
            union { __half2 h2[8]; uint4 u[2]; } hi, lo;
            const float* f = reinterpret_cast<const float*>(av);
#pragma unroll
            for (int j = 0; j < 8; j++) {
                float a0 = f[2 * j], a1 = f[2 * j + 1];
                __half h0 = __float2half_rn(a0);
                __half h1 = __float2half_rn(a1);
                hi.h2[j] = __halves2half2(h0, h1);
                lo.h2[j] = __halves2half2(
                    __float2half_rn(a0 - __half2float(h0)),
                    __float2half_rn(a1 - __half2float(h1)));
            }
            char* pa = smem + ar * LDS_STRIDE + ah * 32;
            *reinterpret_cast<uint4*>(pa + SM_AH) = hi.u[0];
            *reinterpret_cast<uint4*>(pa + SM_AH + 16) = hi.u[1];
            *reinterpret_cast<uint4*>(pa + SM_AL) = lo.u[0];
            *reinterpret_cast<uint4*>(pa + SM_AL + 16) = lo.u[1];
        }
        {
            char* pb = smem + SM_BH + br * LDS_STRIDE + bq * (16 * BVEC);
#pragma unroll
            for (int i = 0; i < BVEC; i++)
                *reinterpret_cast<uint4*>(pb + i * 16) = bhv[i];
        }
        __syncthreads();

        if (kc + 1 < 16) load_tile(kc + 1);

#pragma unroll
        for (int ks = 0; ks < 2; ks++) {
            uint32_t aH[2][4], aL[2][4], bH[NG][4];
#pragma unroll
            for (int mi = 0; mi < 2; mi++) {
                uint32_t addr = a_lm + mi * 16 * LDS_STRIDE + ks * 32;
                ldmx4(aH[mi], addr);
                ldmx4(aL[mi], addr + (SM_AL - SM_AH));
            }
#pragma unroll
            for (int ng = 0; ng < NG; ng++) {
                uint32_t addr = b_lm + ng * 16 * LDS_STRIDE + ks * 32;
                ldmx4(bH[ng], addr);
            }
#pragma unroll
            for (int mi = 0; mi < 2; mi++) {
#pragma unroll
                for (int ng = 0; ng < NG; ng++) {
#pragma unroll
                    for (int nb = 0; nb < 2; nb++) {
                        int ni = ng * 2 + nb;
                        uint32_t bh2[2] = {bH[ng][nb], bH[ng][nb + 2]};
                        mma_fp16(acc[mi][ni], aH[mi], bh2);
                        mma_fp16(acc[mi][ni], aL[mi], bh2);
                    }
                }
            }
        }
    }

    const int g = lane >> 2;
    const int t4 = lane & 3;
#pragma unroll
    for (int mi = 0; mi < 2; mi++) {
#pragma unroll
        for (int ni = 0; ni < NI; ni++) {
            int col = n0 + wn * (BN / 2) + ni * 8 + t4 * 2;
            int row0 = m0 + wm * 32 + mi * 16 + g;
            int row1 = row0 + 8;
            float2 v0 = make_float2(acc[mi][ni][0], acc[mi][ni][1]);
            float2 v1 = make_float2(acc[mi][ni][2], acc[mi][ni][3]);
            if (RELU) {
                v0.x = fmaxf(v0.x, 0.f); v0.y = fmaxf(v0.y, 0.f);
                v1.x = fmaxf(v1.x, 0.f); v1.y = fmaxf(v1.y, 0.f);
            }
            if (row0 < M)
                *reinterpret_cast<float2*>(C + (size_t)row0 * N + col) = v0;
            if (row1 < M)
                *reinterpret_cast<float2*>(C + (size_t)row1 * N + col) = v1;
        }
    }
}

// ---------------------------------------------------------------------------
// launch
// ---------------------------------------------------------------------------
extern "C" void kernel_launch(void* const* d_in, const int* in_sizes, int n_in,
                              void* d_out, int out_size) {
    const float* x = (const float*)d_in[0];
    const int* ei = (const int*)d_in[1];
    const float* W1 = (const float*)d_in[2];
    const float* W2 = (const float*)d_in[3];
    float* out = (float*)d_out;

    const int* src = ei;
    const int* dst = ei + N_EDGES;

    float *h1, *h2;
    int *deg, *off, *cursor, *adj;
    __half *w1h, *w2h, *xh;
    cudaGetSymbolAddress((void**)&h1, g_buf0);
    cudaGetSymbolAddress((void**)&h2, g_buf1);
    cudaGetSymbolAddress((void**)&deg, g_deg);
    cudaGetSymbolAddress((void**)&off, g_off);
    cudaGetSymbolAddress((void**)&cursor, g_cursor);
    cudaGetSymbolAddress((void**)&adj, g_adj);
    cudaGetSymbolAddress((void**)&w1h, g_w1_h);
    cudaGetSymbolAddress((void**)&w2h, g_w2_h);
    cudaGetSymbolAddress((void**)&xh, g_x_h);

    // merged rounding: x, W1, W2 -> fp16
    round_all<<<(N4_ALL + 255) / 256, 256>>>(
        (const float4*)x, (const float4*)W1, (const float4*)W2,
        (uint2*)xh, (uint2*)w1h, (uint2*)w2h);

    // CSR build (by destination)
    csr_zero_deg<<<(N_NODES + 255) / 256, 256>>>(deg);
    csr_hist<<<(N_EDGES + 255) / 256, 256>>>(dst, deg);
    csr_scan<<<1, 1024>>>(deg, off, cursor);
    csr_fill<<<(N_EDGES + 255) / 256, 256>>>(src, dst, cursor, adj);

    const int n_mtiles = (N_NODES + 127) / 128;  // 157

    // propagate 1: h1(fp32) = segment_sum(x_h[src] -> dst), uint4 gather
    gather_prop_h<<<(N_NODES + 1) / 2, 128>>>((const uint4*)xh, off, adj,
                                              (float4*)h1);

    // GEMM1 + ReLU: h2 = relu(h1 @ W1^T)   [20000, 512]
    {
        dim3 grid(n_mtiles, D_IN / 128);
        gemm_mma<128, true><<<grid, 256>>>(h1, w1h, h2, N_NODES, D_IN);
    }

    // GEMM2 first (P commutes with right-mul): z = h2 @ W2^T  [20000, 64]
    {
        dim3 grid(n_mtiles, 1);
        gemm_mma<64, false><<<grid, 256>>>(h2, w2h, h1, N_NODES, D_OUT);
    }

    // propagate 2 (64-wide) + fused log_softmax
    gather64_softmax<<<(N_NODES + 7) / 8, 256>>>(h1, off, adj, out);
}

// round 16
// speedup vs baseline: 1.1366x; 1.1366x over previous
#include <cuda_runtime.h>
#include <cuda_fp16.h>
#include <cstdint>

#define N_NODES 20000
#define D_IN 512
#define D_OUT 64
#define N_EDGES 160000
#define N_PAD 20480                   // 1024 threads * 20 items

// ---------------------------------------------------------------------------
// device globals (no allocation allowed)
// ---------------------------------------------------------------------------
__device__ float g_buf0[(size_t)N_NODES * D_IN];   // h1 fp32, later z fp32
__device__ float g_buf1[(size_t)N_NODES * D_IN];   // h2 fp32
__device__ __half g_x_h[(size_t)N_NODES * D_IN];   // x rounded to fp16
__device__ int g_deg[N_PAD];
__device__ int g_off[N_PAD + 1];
__device__ int g_cursor[N_PAD];
__device__ int g_adj[N_EDGES];
__device__ __half g_w1_h[D_IN * D_IN];
__device__ __half g_w2_h[D_OUT * D_IN];

// ---------------------------------------------------------------------------
// Merged prep: round x/W1/W2 to fp16 AND zero deg, one kernel
// ---------------------------------------------------------------------------
#define N4_X (N_NODES * D_IN / 4)     // 2,560,000
#define N4_W1 (D_IN * D_IN / 4)       // 65,536
#define N4_W2 (D_OUT * D_IN / 4)      // 8,192
#define N4_DEG (N_PAD / 4)            // 5,120
#define N4_ALL (N4_X + N4_W1 + N4_W2 + N4_DEG)

__device__ __forceinline__ uint2 f4_to_h4(float4 v) {
    union { __half2 h2[2]; uint2 u; } o;
    o.h2[0] = __floats2half2_rn(v.x, v.y);
    o.h2[1] = __floats2half2_rn(v.z, v.w);
    return o.u;
}

__global__ void prep_all(const float4* __restrict__ x,
                         const float4* __restrict__ w1,
                         const float4* __restrict__ w2,
                         uint2* __restrict__ xh,
                         uint2* __restrict__ w1h,
                         uint2* __restrict__ w2h,
                         int4* __restrict__ deg4) {
    int i = blockIdx.x * blockDim.x + threadIdx.x;
    if (i < N4_X) {
        xh[i] = f4_to_h4(x[i]);
    } else if (i < N4_X + N4_W1) {
        int j = i - N4_X;
        w1h[j] = f4_to_h4(w1[j]);
    } else if (i < N4_X + N4_W1 + N4_W2) {
        int j = i - N4_X - N4_W1;
        w2h[j] = f4_to_h4(w2[j]);
    } else if (i < N4_ALL) {
        int j = i - N4_X - N4_W1 - N4_W2;
        deg4[j] = make_int4(0, 0, 0, 0);
    }
}

// ---------------------------------------------------------------------------
// CSR build
// ---------------------------------------------------------------------------
__global__ void csr_hist(const int* __restrict__ dst, int* __restrict__ deg) {
    int e = blockIdx.x * blockDim.x + threadIdx.x;
    if (e < N_EDGES) atomicAdd(&deg[dst[e]], 1);
}

// Single-block exclusive scan with smem staging (coalesced global I/O).
// deg padded to N_PAD with zeros, so off[N_NODES]=total falls out of stage-out.
__global__ void csr_scan(const int* __restrict__ deg, int* __restrict__ off,
                         int* __restrict__ cursor) {
    extern __shared__ int sdeg[];     // N_PAD ints = 80 KB
    __shared__ int wsum[32];
    const int t = threadIdx.x;
    const int lane = t & 31;
    const int warp = t >> 5;

    // coalesced stage-in (5 int4 per thread)
    int4* s4 = reinterpret_cast<int4*>(sdeg);
    const int4* d4 = reinterpret_cast<const int4*>(deg);
#pragma unroll
    for (int i = 0; i < 5; i++) s4[t + i * 1024] = d4[t + i * 1024];
    __syncthreads();

    // per-thread serial scan over contiguous 20 items (from smem)
    const int base = t * 20;
    int local[20];
    int s = 0;
#pragma unroll
    for (int i = 0; i < 20; i++) {
        local[i] = s;
        s += sdeg[base + i];
    }
    // warp-level inclusive scan of per-thread sums
    int incl = s;
#pragma unroll
    for (int d = 1; d < 32; d <<= 1) {
        int v = __shfl_up_sync(0xffffffffu, incl, d);
        if (lane >= d) incl += v;
    }
    if (lane == 31) wsum[warp] = incl;
    __syncthreads();
    if (warp == 0) {
        int v = wsum[lane];
        int winc = v;
#pragma unroll
        for (int d = 1; d < 32; d <<= 1) {
            int u = __shfl_up_sync(0xffffffffu, winc, d);
            if (lane >= d) winc += u;
        }
        wsum[lane] = winc - v;   // exclusive warp base
    }
    __syncthreads();
    const int tbase = wsum[warp] + (incl - s);

    // write exclusive prefixes back into own smem chunk (no race: own chunk)
#pragma unroll
    for (int i = 0; i < 20; i++) sdeg[base + i] = tbase + local[i];
    __syncthreads();

    // coalesced stage-out to off and cursor
    int4* o4 = reinterpret_cast<int4*>(off);
    int4* c4 = reinterpret_cast<int4*>(cursor);
#pragma unroll
    for (int i = 0; i < 5; i++) {
        int4 v = s4[t + i * 1024];
        o4[t + i * 1024] = v;
        c4[t + i * 1024] = v;
    }
    // off[idx >= N_NODES] == total already (padded zeros); off[N_NODES] valid.
}

__global__ void csr_fill(const int* __restrict__ src, const int* __restrict__ dst,
                         int* __restrict__ cursor, int* __restrict__ adj) {
    int e = blockIdx.x * blockDim.x + threadIdx.x;
    if (e < N_EDGES) {
        int p = atomicAdd(&cursor[dst[e]], 1);
        adj[p] = src[e];
    }
}

// ---------------------------------------------------------------------------
// Gather propagate: fp16 x in via uint4 (8 halves/load), fp32 out.
// 64 threads per node, 2 nodes per 128-thread block.
// ---------------------------------------------------------------------------
__global__ void gather_prop_h(const uint4* __restrict__ xh,  // [N, 64] uint4
                              const int* __restrict__ off,
                              const int* __restrict__ adj,
                              float4* __restrict__ out) {    // [N, 128] float4
    const int node = blockIdx.x * 2 + (threadIdx.x >> 6);
    const int t = threadIdx.x & 63;
    if (node >= N_NODES) return;
    int b = off[node];
    int e = off[node + 1];
    float acc[8] = {0.f, 0.f, 0.f, 0.f, 0.f, 0.f, 0.f, 0.f};

    auto add8 = [&](uint4 v) {
        union { uint4 u; __half2 h[4]; } w;
        w.u = v;
#pragma unroll
        for (int j = 0; j < 4; j++) {
            float2 f = __half22float2(w.h[j]);
            acc[2 * j] += f.x;
            acc[2 * j + 1] += f.y;
        }
    };

    int i = b;
    for (; i + 1 < e; i += 2) {
        uint4 v0 = xh[(size_t)adj[i] * 64 + t];
        uint4 v1 = xh[(size_t)adj[i + 1] * 64 + t];
        add8(v0);
        add8(v1);
    }
    if (i < e) add8(xh[(size_t)adj[i] * 64 + t]);

    float4* op = out + (size_t)node * 128 + t * 2;
    op[0] = make_float4(acc[0], acc[1], acc[2], acc[3]);
    op[1] = make_float4(acc[4], acc[5], acc[6], acc[7]);
}

// ---------------------------------------------------------------------------
// Gather propagate 64-wide + fused log_softmax (one warp per node, float2)
// ---------------------------------------------------------------------------
__global__ void gather64_softmax(const float* __restrict__ z,
                                 const int* __restrict__ off,
                                 const int* __restrict__ adj,
                                 float* __restrict__ out) {
    const int node = blockIdx.x * (blockDim.x >> 5) + (threadIdx.x >> 5);
    const int lane = threadIdx.x & 31;
    if (node >= N_NODES) return;
    int b = off[node];
    int e = off[node + 1];
    float a0 = 0.f, a1 = 0.f;
    for (int i = b; i < e; i++) {
        float2 v = *reinterpret_cast<const float2*>(
            z + (size_t)adj[i] * D_OUT + lane * 2);
        a0 += v.x;
        a1 += v.y;
    }
    float mx = fmaxf(a0, a1);
#pragma unroll
    for (int o = 16; o > 0; o >>= 1)
        mx = fmaxf(mx, __shfl_xor_sync(0xffffffffu, mx, o));
    float s = expf(a0 - mx) + expf(a1 - mx);
#pragma unroll
    for (int o = 16; o > 0; o >>= 1)
        s += __shfl_xor_sync(0xffffffffu, s, o);
    float l = mx + logf(s);
    *reinterpret_cast<float2*>(out + (size_t)node * D_OUT + lane * 2) =
        make_float2(a0 - l, a1 - l);
}

// ---------------------------------------------------------------------------
// mma.sync helpers (fp16 inputs, fp32 accumulate)
// ---------------------------------------------------------------------------
__device__ __forceinline__ void mma_fp16(float* d, const uint32_t* a,
                                         const uint32_t* b) {
    asm volatile(
        "mma.sync.aligned.m16n8k16.row.col.f32.f16.f16.f32 "
        "{%0,%1,%2,%3}, {%4,%5,%6,%7}, {%8,%9}, {%0,%1,%2,%3};"
        : "+f"(d[0]), "+f"(d[1]), "+f"(d[2]), "+f"(d[3])
        : "r"(a[0]), "r"(a[1]), "r"(a[2]), "r"(a[3]), "r"(b[0]), "r"(b[1]));
}

__device__ __forceinline__ void ldmx4(uint32_t* r, uint32_t addr) {
    asm volatile(
        "ldmatrix.sync.aligned.m8n8.x4.shared.b16 {%0,%1,%2,%3}, [%4];"
        : "=r"(r[0]), "=r"(r[1]), "=r"(r[2]), "=r"(r[3])
        : "r"(addr));
}

// ---------------------------------------------------------------------------
// fp16 2-term split GEMM via mma.sync: C[M,N] = A[M,512] * B[N,512]^T
// A fp32 -> fp16 hi+lo inline; B pre-rounded fp16.
// CTA tile 128 x BN, BK=32, 8 warps each 32 x (BN/2).
// ---------------------------------------------------------------------------
#define LDS_STRIDE 80

template <int BN, bool RELU>
__global__ __launch_bounds__(256)
void gemm_mma(const float* __restrict__ A,
              const __half* __restrict__ Bh,
              float* __restrict__ C, int M, int N) {
    constexpr int NI = BN / 16;
    constexpr int NG = BN / 32;
    constexpr int SM_AH = 0;
    constexpr int SM_AL = 128 * LDS_STRIDE;
    constexpr int SM_BH = 2 * 128 * LDS_STRIDE;
    constexpr int SM_TOTAL = SM_BH + BN * LDS_STRIDE;
    constexpr int BPR = 256 / BN;
    constexpr int BVEC = 4 / BPR;

    __shared__ __align__(16) char smem[SM_TOTAL];
    const int tid = threadIdx.x;
    const int lane = tid & 31;
    const int wid = tid >> 5;
    const int wm = wid & 3;
    const int wn = wid >> 2;
    const int m0 = blockIdx.x * 128;
    const int n0 = blockIdx.y * BN;

    const uint32_t sb = (uint32_t)__cvta_generic_to_shared(smem);

    float acc[2][NI][4];
#pragma unroll
    for (int i = 0; i < 2; i++)
#pragma unroll
        for (int j = 0; j < NI; j++)
#pragma unroll
            for (int k = 0; k < 4; k++) acc[i][j][k] = 0.f;

    const int ar = tid >> 1;
    const int ah = tid & 1;
    const bool arow_ok = (m0 + ar) < M;
    const int br = tid / BPR;
    const int bq = tid % BPR;

    const uint32_t a_lm = sb + (uint32_t)((wm * 32 + (lane & 15)) * LDS_STRIDE +
                                          (lane >> 4) * 16);
    const uint32_t b_lm = sb + SM_BH +
        (uint32_t)((wn * (BN / 2) + (lane & 15)) * LDS_STRIDE + (lane >> 4) * 16);

    float4 av[4];
    uint4 bhv[BVEC];

    auto load_tile = [&](int kc) {
        if (arow_ok) {
            const float4* ap = reinterpret_cast<const float4*>(
                A + (size_t)(m0 + ar) * D_IN + kc * 32 + ah * 16);
#pragma unroll
            for (int i = 0; i < 4; i++) av[i] = ap[i];
        } else {
#pragma unroll
            for (int i = 0; i < 4; i++) av[i] = make_float4(0.f, 0.f, 0.f, 0.f);
        }
        const uint4* bh = reinterpret_cast<const uint4*>(
            Bh + (size_t)(n0 + br) * D_IN + kc * 32 + bq * (8 * BVEC));
#pragma unroll
        for (int i = 0; i < BVEC; i++) bhv[i] = bh[i];
    };

    load_tile(0);

    for (int kc = 0; kc < 16; kc++) {
        __syncthreads();

        {
            union { __half2 h2[8]; uint4 u[2]; } hi, lo;
            const float* f = reinterpret_cast<const float*>(av);
#pragma unroll
            for (int j = 0; j < 8; j++) {
                float a0 = f[2 * j], a1 = f[2 * j + 1];
                __half h0 = __float2half_rn(a0);
                __half h1 = __float2half_rn(a1);
                hi.h2[j] = __halves2half2(h0, h1);
                lo.h2[j] = __halves2half2(
                    __float2half_rn(a0 - __half2float(h0)),
                    __float2half_rn(a1 - __half2float(h1)));
            }
            char* pa = smem + ar * LDS_STRIDE + ah * 32;
            *reinterpret_cast<uint4*>(pa + SM_AH) = hi.u[0];
            *reinterpret_cast<uint4*>(pa + SM_AH + 16) = hi.u[1];
            *reinterpret_cast<uint4*>(pa + SM_AL) = lo.u[0];
            *reinterpret_cast<uint4*>(pa + SM_AL + 16) = lo.u[1];
        }
        {
            char* pb = smem + SM_BH + br * LDS_STRIDE + bq * (16 * BVEC);
#pragma unroll
            for (int i = 0; i < BVEC; i++)
                *reinterpret_cast<uint4*>(pb + i * 16) = bhv[i];
        }
        __syncthreads();

        if (kc + 1 < 16) load_tile(kc + 1);

#pragma unroll
        for (int ks = 0; ks < 2; ks++) {
            uint32_t aH[2][4], aL[2][4], bH[NG][4];
#pragma unroll
            for (int mi = 0; mi < 2; mi++) {
                uint32_t addr = a_lm + mi * 16 * LDS_STRIDE + ks * 32;
                ldmx4(aH[mi], addr);
                ldmx4(aL[mi], addr + (SM_AL - SM_AH));
            }
#pragma unroll
            for (int ng = 0; ng < NG; ng++) {
                uint32_t addr = b_lm + ng * 16 * LDS_STRIDE + ks * 32;
                ldmx4(bH[ng], addr);
            }
#pragma unroll
            for (int mi = 0; mi < 2; mi++) {
#pragma unroll
                for (int ng = 0; ng < NG; ng++) {
#pragma unroll
                    for (int nb = 0; nb < 2; nb++) {
                        int ni = ng * 2 + nb;
                        uint32_t bh2[2] = {bH[ng][nb], bH[ng][nb + 2]};
                        mma_fp16(acc[mi][ni], aH[mi], bh2);
                        mma_fp16(acc[mi][ni], aL[mi], bh2);
                    }
                }
            }
        }
    }

    const int g = lane >> 2;
    const int t4 = lane & 3;
#pragma unroll
    for (int mi = 0; mi < 2; mi++) {
#pragma unroll
        for (int ni = 0; ni < NI; ni++) {
            int col = n0 + wn * (BN / 2) + ni * 8 + t4 * 2;
            int row0 = m0 + wm * 32 + mi * 16 + g;
            int row1 = row0 + 8;
            float2 v0 = make_float2(acc[mi][ni][0], acc[mi][ni][1]);
            float2 v1 = make_float2(acc[mi][ni][2], acc[mi][ni][3]);
            if (RELU) {
                v0.x = fmaxf(v0.x, 0.f); v0.y = fmaxf(v0.y, 0.f);
                v1.x = fmaxf(v1.x, 0.f); v1.y = fmaxf(v1.y, 0.f);
            }
            if (row0 < M)
                *reinterpret_cast<float2*>(C + (size_t)row0 * N + col) = v0;
            if (row1 < M)
                *reinterpret_cast<float2*>(C + (size_t)row1 * N + col) = v1;
        }
    }
}

// ---------------------------------------------------------------------------
// launch
// ---------------------------------------------------------------------------
extern "C" void kernel_launch(void* const* d_in, const int* in_sizes, int n_in,
                              void* d_out, int out_size) {
    const float* x = (const float*)d_in[0];
    const int* ei = (const int*)d_in[1];
    const float* W1 = (const float*)d_in[2];
    const float* W2 = (const float*)d_in[3];
    float* out = (float*)d_out;

    const int* src = ei;
    const int* dst = ei + N_EDGES;

    float *h1, *h2;
    int *deg, *off, *cursor, *adj;
    __half *w1h, *w2h, *xh;
    cudaGetSymbolAddress((void**)&h1, g_buf0);
    cudaGetSymbolAddress((void**)&h2, g_buf1);
    cudaGetSymbolAddress((void**)&deg, g_deg);
    cudaGetSymbolAddress((void**)&off, g_off);
    cudaGetSymbolAddress((void**)&cursor, g_cursor);
    cudaGetSymbolAddress((void**)&adj, g_adj);
    cudaGetSymbolAddress((void**)&w1h, g_w1_h);
    cudaGetSymbolAddress((void**)&w2h, g_w2_h);
    cudaGetSymbolAddress((void**)&xh, g_x_h);

    static bool attr_done = false;
    if (!attr_done) {
        cudaFuncSetAttribute(csr_scan,
                             cudaFuncAttributeMaxDynamicSharedMemorySize,
                             N_PAD * (int)sizeof(int));
        attr_done = true;
    }

    // merged prep: round x/W1/W2 to fp16, zero deg
    prep_all<<<(N4_ALL + 255) / 256, 256>>>(
        (const float4*)x, (const float4*)W1, (const float4*)W2,
        (uint2*)xh, (uint2*)w1h, (uint2*)w2h, (int4*)deg);

    // CSR build (by destination)
    csr_hist<<<(N_EDGES + 255) / 256, 256>>>(dst, deg);
    csr_scan<<<1, 1024, N_PAD * sizeof(int)>>>(deg, off, cursor);
    csr_fill<<<(N_EDGES + 255) / 256, 256>>>(src, dst, cursor, adj);

    const int n_mtiles = (N_NODES + 127) / 128;  // 157

    // propagate 1: h1(fp32) = segment_sum(x_h[src] -> dst), uint4 gather
    gather_prop_h<<<(N_NODES + 1) / 2, 128>>>((const uint4*)xh, off, adj,
                                              (float4*)h1);

    // GEMM1 + ReLU: h2 = relu(h1 @ W1^T)   [20000, 512]
    {
        dim3 grid(n_mtiles, D_IN / 128);
        gemm_mma<128, true><<<grid, 256>>>(h1, w1h, h2, N_NODES, D_IN);
    }

    // GEMM2 first (P commutes with right-mul): z = h2 @ W2^T  [20000, 64]
    {
        dim3 grid(n_mtiles, 1);
        gemm_mma<64, false><<<grid, 256>>>(h2, w2h, h1, N_NODES, D_OUT);
    }

    // propagate 2 (64-wide) + fused log_softmax
    gather64_softmax<<<(N_NODES + 7) / 8, 256>>>(h1, off, adj, out);
}